// round 15
// baseline (speedup 1.0000x reference)
#include <cuda_runtime.h>
#include <cuda_bf16.h>
#include <cstdint>

#define N_NODES 200000
#define N_EDGES 6400000
#define N_LAYERS 3

// Scratch (no cudaMalloc allowed). Zero at module load; every kernel_launch
// leaves them zeroed again (last reader re-zeroes), so graph replays are
// deterministic.
__device__ float4 g_T[N_NODES];    // (t0, t1, t2, deg) accumulators
__device__ float  g_A[N_NODES];    // current per-node cumulative scalar
__device__ float  g_q1[N_NODES];   // M @ A_1
__device__ float  g_q2[N_NODES];   // M @ A_2
// per-layer 16 floats: [0..11]=W row, [12]=b, [13]=sA=sum(w[0:4]), [14]=sB=sum(w[4:8])
__device__ float  g_wc[N_LAYERS * 16];

// PDL primitives
__device__ __forceinline__ void pdl_wait() {
    asm volatile("griddepcontrol.wait;" ::: "memory");
}
__device__ __forceinline__ void pdl_trigger() {
    asm volatile("griddepcontrol.launch_dependents;" ::: "memory");
}

// ---------------------------------------------------------------------------
// 1. init: single warp computes per-layer weight constants. T/q1/q2 are
//    already zero (loader or previous replay's re-zeroing). Early trigger so
//    the heavy pass ramps immediately.
// ---------------------------------------------------------------------------
__global__ void init_kernel(const float* __restrict__ W,
                            const float* __restrict__ b) {
    int i = threadIdx.x;
    if (i < N_LAYERS) {
        float sA = 0.f, sB = 0.f;
        #pragma unroll
        for (int j = 0; j < 12; j++) {
            float w = W[i * 12 + j];
            g_wc[i * 16 + j] = w;
            if (j < 4)       sA += w;
            else if (j < 8)  sB += w;
        }
        g_wc[i * 16 + 12] = b[i];
        g_wc[i * 16 + 13] = sA;
        g_wc[i * 16 + 14] = sB;
    }
    pdl_trigger();
}

// ---------------------------------------------------------------------------
__device__ __forceinline__ void red_add_v4(float4* ptr, float a, float b,
                                           float c, float d) {
    asm volatile("red.global.add.v4.f32 [%0], {%1, %2, %3, %4};"
                 :: "l"(__cvta_generic_to_global(ptr)),
                    "f"(a), "f"(b), "f"(c), "f"(d)
                 : "memory");
}

// ---------------------------------------------------------------------------
// 2. ONE heavy edge pass for all 3 layers, 4 edges per thread:
//    T[dst] += ( ws_l.z0[src] + w_geo_l.(r,rhat)  for l=0..2 , 1 )
//    Input loads hoisted above pdl_wait. No explicit trigger (the dependent
//    node kernel needs full completion — prevents LTS-bound co-residency).
// ---------------------------------------------------------------------------
__global__ void __launch_bounds__(256)
heavy_edge_kernel(const int4* __restrict__ src4,
                  const int4* __restrict__ dst4,
                  const float4* __restrict__ r4,
                  const float4* __restrict__ rhat4,
                  const float4* __restrict__ z0,
                  float4* __restrict__ T) {
    int t = blockIdx.x * blockDim.x + threadIdx.x;   // grid is exact: no OOB

    int4   s  = __ldcs(src4 + t);
    int4   d  = __ldcs(dst4 + t);
    float4 r  = __ldcs(r4   + t);
    float4 h0 = __ldcs(rhat4 + 3 * t + 0);
    float4 h1 = __ldcs(rhat4 + 3 * t + 1);
    float4 h2 = __ldcs(rhat4 + 3 * t + 2);

    float4 zs0 = __ldg(&z0[s.x]);
    float4 zs1 = __ldg(&z0[s.y]);
    float4 zs2 = __ldg(&z0[s.z]);
    float4 zs3 = __ldg(&z0[s.w]);

    pdl_wait();   // g_wc written by init (T already zero by invariant)

    float rr[4]    = {r.x, r.y, r.z, r.w};
    float rh[4][3] = {{h0.x, h0.y, h0.z}, {h0.w, h1.x, h1.y},
                      {h1.z, h1.w, h2.x}, {h2.y, h2.z, h2.w}};
    float4 zs[4]   = {zs0, zs1, zs2, zs3};
    int    dd[4]   = {d.x, d.y, d.z, d.w};

    float tv[4][3];
    #pragma unroll
    for (int l = 0; l < N_LAYERS; l++) {
        const float* wc = g_wc + l * 16;
        float w0 = wc[0], w1 = wc[1], w2 = wc[2], w3 = wc[3];
        float w8 = wc[8], w9 = wc[9], wa = wc[10], wb = wc[11];
        #pragma unroll
        for (int e = 0; e < 4; e++) {
            tv[e][l] = w0 * zs[e].x + w1 * zs[e].y + w2 * zs[e].z + w3 * zs[e].w
                     + w8 * rr[e] + w9 * rh[e][0] + wa * rh[e][1] + wb * rh[e][2];
        }
    }

    #pragma unroll
    for (int e = 0; e < 4; e++)
        red_add_v4(&T[dd[e]], tv[e][0], tv[e][1], tv[e][2], 1.f);
}

// ---------------------------------------------------------------------------
// 3. Light edge pass, 4 edges per thread: q[dst] += A[src]
// ---------------------------------------------------------------------------
__global__ void __launch_bounds__(256)
light_edge_kernel(const int4* __restrict__ src4,
                  const int4* __restrict__ dst4,
                  const float* __restrict__ A,
                  float* __restrict__ q) {
    int t = blockIdx.x * blockDim.x + threadIdx.x;   // grid is exact: no OOB

    int4 s = __ldcs(src4 + t);
    int4 d = __ldcs(dst4 + t);

    pdl_wait();   // A from preceding node kernel (q already zero by invariant)

    float a0 = __ldg(&A[s.x]);
    float a1 = __ldg(&A[s.y]);
    float a2 = __ldg(&A[s.z]);
    float a3 = __ldg(&A[s.w]);

    atomicAdd(&q[d.x], a0);
    atomicAdd(&q[d.y], a1);
    atomicAdd(&q[d.z], a2);
    atomicAdd(&q[d.w], a3);
}

// ---------------------------------------------------------------------------
// 4. Node update layer 0: A1 = t0 + deg*(b0 + wd0.z0)   (A0 = 0, q0 = 0)
//    Writes out_x = z0. Early trigger after stores.
// ---------------------------------------------------------------------------
__global__ void node0_kernel(const float4* __restrict__ z0,
                             const float4* __restrict__ T,
                             float* __restrict__ A,
                             float4* __restrict__ out) {
    int n = blockIdx.x * blockDim.x + threadIdx.x;
    bool ok = (n < N_NODES);
    float4 z = make_float4(0.f, 0.f, 0.f, 0.f);
    if (ok) z = z0[n];
    pdl_wait();   // T from heavy pass (full completion)
    if (ok) {
        const float* wc = g_wc;  // layer 0
        float4 tt = T[n];
        float pd = wc[12] + wc[4]*z.x + wc[5]*z.y + wc[6]*z.z + wc[7]*z.w;
        A[n] = tt.x + tt.w * pd;
        out[N_NODES + n] = z;     // x output
    }
    pdl_trigger();
}

// ---------------------------------------------------------------------------
// 5. Node update layer 1: A2 = A1 + t1 + sA1*q1 + deg*(b1 + wd1.z0 + sB1*A1)
//    Re-zeroes q1 after reading (replay invariant). Early trigger.
// ---------------------------------------------------------------------------
__global__ void node_update1_kernel(const float4* __restrict__ z0,
                                    const float4* __restrict__ T,
                                    float* __restrict__ q,
                                    float* __restrict__ A) {
    int n = blockIdx.x * blockDim.x + threadIdx.x;
    bool ok = (n < N_NODES);
    float4 z = make_float4(0.f, 0.f, 0.f, 0.f);
    if (ok) z = z0[n];
    pdl_wait();   // q1 from light pass 1 (full completion)
    if (ok) {
        const float* wc = g_wc + 16;  // layer 1
        float4 tt = T[n];
        float  a = A[n];
        float qv = q[n];
        q[n] = 0.f;   // restore zero-invariant for next replay
        float pd = wc[12] + wc[4]*z.x + wc[5]*z.y + wc[6]*z.z + wc[7]*z.w + wc[14]*a;
        A[n] = a + tt.y + wc[13] * qv + tt.w * pd;
    }
    pdl_trigger();
}

// ---------------------------------------------------------------------------
// 6. Node update layer 2 + finalize:
//    A3 = A2 + t2 + sA2*q2 + deg*(b2 + wd2.z0 + sB2*A2);  out_z = z0 + A3
//    Re-zeroes T and q2 after reading (replay invariant).
// ---------------------------------------------------------------------------
__global__ void node_update2_final_kernel(const float4* __restrict__ z0,
                                          float4* __restrict__ T,
                                          float* __restrict__ q,
                                          const float* __restrict__ A,
                                          float4* __restrict__ out) {
    int n = blockIdx.x * blockDim.x + threadIdx.x;
    bool ok = (n < N_NODES);
    float4 z = make_float4(0.f, 0.f, 0.f, 0.f);
    if (ok) z = z0[n];
    pdl_wait();   // q2 from light pass 2 (full completion)
    if (!ok) return;
    const float* wc = g_wc + 32;  // layer 2
    float4 tt = T[n];
    float  a = A[n];
    float  qv = q[n];
    T[n] = make_float4(0.f, 0.f, 0.f, 0.f);   // restore zero-invariant
    q[n] = 0.f;
    float pd = wc[12] + wc[4]*z.x + wc[5]*z.y + wc[6]*z.z + wc[7]*z.w + wc[14]*a;
    float a3 = a + tt.z + wc[13] * qv + tt.w * pd;
    out[n] = make_float4(z.x + a3, z.y + a3, z.z + a3, z.w + a3);
}

// ---------------------------------------------------------------------------
// PDL launch helper
// ---------------------------------------------------------------------------
template <typename... Args>
static void launch_pdl(void (*kern)(Args...), dim3 grid, dim3 block,
                       Args... args) {
    cudaLaunchAttribute attr[1];
    attr[0].id = cudaLaunchAttributeProgrammaticStreamSerialization;
    attr[0].val.programmaticStreamSerializationAllowed = 1;
    cudaLaunchConfig_t cfg = {};
    cfg.gridDim = grid;
    cfg.blockDim = block;
    cfg.dynamicSmemBytes = 0;
    cfg.stream = 0;
    cfg.attrs = attr;
    cfg.numAttrs = 1;
    cudaLaunchKernelEx(&cfg, kern, args...);
}

// ---------------------------------------------------------------------------
extern "C" void kernel_launch(void* const* d_in, const int* in_sizes, int n_in,
                              void* d_out, int out_size) {
    const float* z    = (const float*)d_in[0];
    const float* r    = (const float*)d_in[1];
    const float* rhat = (const float*)d_in[2];
    const float* W    = (const float*)d_in[3];
    const float* b    = (const float*)d_in[4];
    const int*   src  = (const int*)d_in[5];
    const int*   dst  = (const int*)d_in[6];
    float* out = (float*)d_out;

    float4 *T; float *A, *q1, *q2;
    cudaGetSymbolAddress((void**)&T,  g_T);
    cudaGetSymbolAddress((void**)&A,  g_A);
    cudaGetSymbolAddress((void**)&q1, g_q1);
    cudaGetSymbolAddress((void**)&q2, g_q2);

    const dim3 blk(256);
    const dim3 NODE_GRID((N_NODES + 255) / 256);
    const dim3 EDGE_GRID(N_EDGES / 4 / 256);   // exact: 6250

    init_kernel<<<1, 32>>>(W, b);

    launch_pdl(heavy_edge_kernel, EDGE_GRID, blk,
               (const int4*)src, (const int4*)dst,
               (const float4*)r, (const float4*)rhat,
               (const float4*)z, T);

    launch_pdl(node0_kernel, NODE_GRID, blk,
               (const float4*)z, (const float4*)T, A, (float4*)out);

    launch_pdl(light_edge_kernel, EDGE_GRID, blk,
               (const int4*)src, (const int4*)dst, (const float*)A, q1);

    launch_pdl(node_update1_kernel, NODE_GRID, blk,
               (const float4*)z, (const float4*)T, q1, A);

    launch_pdl(light_edge_kernel, EDGE_GRID, blk,
               (const int4*)src, (const int4*)dst, (const float*)A, q2);

    launch_pdl(node_update2_final_kernel, NODE_GRID, blk,
               (const float4*)z, T, q2, (const float*)A, (float4*)out);
}

// round 16
// speedup vs baseline: 1.0467x; 1.0467x over previous
#include <cuda_runtime.h>
#include <cuda_bf16.h>
#include <cstdint>

#define N_NODES 200000
#define N_EDGES 6400000
#define N_LAYERS 3

// Scratch (no cudaMalloc allowed)
__device__ float4 g_T[N_NODES];    // (t0, t1, t2, deg) accumulators
__device__ float  g_A1[N_NODES];   // layer-1 per-node scalar
__device__ float2 g_P[N_NODES];    // (c, q1): c node-local, q1 RED'd by pass 1
__device__ float  g_q2[N_NODES];   // M @ A_2
// per-layer 16 floats: [0..11]=W row, [12]=b, [13]=sA=sum(w[0:4]), [14]=sB=sum(w[4:8])
__device__ float  g_wc[N_LAYERS * 16];

// PDL primitive: wait for stream predecessor (implicit trigger at completion)
__device__ __forceinline__ void pdl_wait() {
    asm volatile("griddepcontrol.wait;" ::: "memory");
}

// ---------------------------------------------------------------------------
// 1. init: zero T and q2; block 0 computes per-layer weight constants
// ---------------------------------------------------------------------------
__global__ void init_kernel(const float* __restrict__ W,
                            const float* __restrict__ b,
                            float4* __restrict__ T,
                            float* __restrict__ q2) {
    int n = blockIdx.x * blockDim.x + threadIdx.x;
    if (blockIdx.x == 0 && threadIdx.x < N_LAYERS) {
        int i = threadIdx.x;
        float sA = 0.f, sB = 0.f;
        #pragma unroll
        for (int j = 0; j < 12; j++) {
            float w = W[i * 12 + j];
            g_wc[i * 16 + j] = w;
            if (j < 4)       sA += w;
            else if (j < 8)  sB += w;
        }
        g_wc[i * 16 + 12] = b[i];
        g_wc[i * 16 + 13] = sA;
        g_wc[i * 16 + 14] = sB;
    }
    if (n < N_NODES) {
        T[n] = make_float4(0.f, 0.f, 0.f, 0.f);
        q2[n] = 0.f;
    }
}

// ---------------------------------------------------------------------------
__device__ __forceinline__ void red_add_v4(float4* ptr, float a, float b,
                                           float c, float d) {
    asm volatile("red.global.add.v4.f32 [%0], {%1, %2, %3, %4};"
                 :: "l"(__cvta_generic_to_global(ptr)),
                    "f"(a), "f"(b), "f"(c), "f"(d)
                 : "memory");
}

// ---------------------------------------------------------------------------
// 2. ONE heavy edge pass for all 3 layers, 4 edges per thread:
//    T[dst] += ( ws_l.z0[src] + w_geo_l.(r,rhat)  for l=0..2 , 1 )
// ---------------------------------------------------------------------------
__global__ void __launch_bounds__(256)
heavy_edge_kernel(const int4* __restrict__ src4,
                  const int4* __restrict__ dst4,
                  const float4* __restrict__ r4,
                  const float4* __restrict__ rhat4,
                  const float4* __restrict__ z0,
                  float4* __restrict__ T) {
    pdl_wait();
    int t = blockIdx.x * blockDim.x + threadIdx.x;   // grid exact: no OOB

    int4   s  = __ldcs(src4 + t);
    int4   d  = __ldcs(dst4 + t);
    float4 r  = __ldcs(r4   + t);
    float4 h0 = __ldcs(rhat4 + 3 * t + 0);
    float4 h1 = __ldcs(rhat4 + 3 * t + 1);
    float4 h2 = __ldcs(rhat4 + 3 * t + 2);

    float4 zs0 = __ldg(&z0[s.x]);
    float4 zs1 = __ldg(&z0[s.y]);
    float4 zs2 = __ldg(&z0[s.z]);
    float4 zs3 = __ldg(&z0[s.w]);

    float rr[4]    = {r.x, r.y, r.z, r.w};
    float rh[4][3] = {{h0.x, h0.y, h0.z}, {h0.w, h1.x, h1.y},
                      {h1.z, h1.w, h2.x}, {h2.y, h2.z, h2.w}};
    float4 zs[4]   = {zs0, zs1, zs2, zs3};
    int    dd[4]   = {d.x, d.y, d.z, d.w};

    float tv[4][3];
    #pragma unroll
    for (int l = 0; l < N_LAYERS; l++) {
        const float* wc = g_wc + l * 16;
        float w0 = wc[0], w1 = wc[1], w2 = wc[2], w3 = wc[3];
        float w8 = wc[8], w9 = wc[9], wa = wc[10], wb = wc[11];
        #pragma unroll
        for (int e = 0; e < 4; e++) {
            tv[e][l] = w0 * zs[e].x + w1 * zs[e].y + w2 * zs[e].z + w3 * zs[e].w
                     + w8 * rr[e] + w9 * rh[e][0] + wa * rh[e][1] + wb * rh[e][2];
        }
    }

    #pragma unroll
    for (int e = 0; e < 4; e++)
        red_add_v4(&T[dd[e]], tv[e][0], tv[e][1], tv[e][2], 1.f);
}

// ---------------------------------------------------------------------------
// 3. Node layer 0/1 prep:
//    A1 = t0 + deg*(b0 + wd0.z0)
//    c  = A1 + t1 + deg*(b1 + wd1.z0 + sB1*A1)
//    P  = (c, 0);  out_x = z0
// ---------------------------------------------------------------------------
__global__ void node0_kernel(const float4* __restrict__ z0,
                             const float4* __restrict__ T,
                             float* __restrict__ A1,
                             float2* __restrict__ P,
                             float4* __restrict__ out) {
    pdl_wait();
    int n = blockIdx.x * blockDim.x + threadIdx.x;
    if (n >= N_NODES) return;
    const float* wc0 = g_wc;        // layer 0
    const float* wc1 = g_wc + 16;   // layer 1
    float4 z = z0[n];
    float4 tt = T[n];
    float pd0 = wc0[12] + wc0[4]*z.x + wc0[5]*z.y + wc0[6]*z.z + wc0[7]*z.w;
    float a1 = tt.x + tt.w * pd0;
    float pd1 = wc1[12] + wc1[4]*z.x + wc1[5]*z.y + wc1[6]*z.z + wc1[7]*z.w
              + wc1[14] * a1;
    float c = a1 + tt.y + tt.w * pd1;
    A1[n] = a1;
    P[n] = make_float2(c, 0.f);
    out[N_NODES + n] = z;           // x output
}

// ---------------------------------------------------------------------------
// 4. Light pass 1: P[dst].y += A1[src]   (q1 accumulation)
// ---------------------------------------------------------------------------
__global__ void __launch_bounds__(256)
light1_kernel(const int4* __restrict__ src4,
              const int4* __restrict__ dst4,
              const float* __restrict__ A1,
              float2* __restrict__ P) {
    pdl_wait();
    int t = blockIdx.x * blockDim.x + threadIdx.x;   // grid exact: no OOB

    int4 s = __ldcs(src4 + t);
    int4 d = __ldcs(dst4 + t);

    float a0 = __ldg(&A1[s.x]);
    float a1 = __ldg(&A1[s.y]);
    float a2 = __ldg(&A1[s.z]);
    float a3 = __ldg(&A1[s.w]);

    atomicAdd(&P[d.x].y, a0);
    atomicAdd(&P[d.y].y, a1);
    atomicAdd(&P[d.z].y, a2);
    atomicAdd(&P[d.w].y, a3);
}

// ---------------------------------------------------------------------------
// 5. Light pass 2: q2[dst] += c[src] + sA1*q1[src]   (= A2[src], on the fly)
//    Single float2 gather replaces the A2 gather — no inter-pass node kernel.
// ---------------------------------------------------------------------------
__global__ void __launch_bounds__(256)
light2_kernel(const int4* __restrict__ src4,
              const int4* __restrict__ dst4,
              const float2* __restrict__ P,
              float* __restrict__ q2) {
    pdl_wait();
    int t = blockIdx.x * blockDim.x + threadIdx.x;   // grid exact: no OOB

    int4 s = __ldcs(src4 + t);
    int4 d = __ldcs(dst4 + t);
    float sA1 = g_wc[16 + 13];

    float2 p0 = __ldg(&P[s.x]);
    float2 p1 = __ldg(&P[s.y]);
    float2 p2 = __ldg(&P[s.z]);
    float2 p3 = __ldg(&P[s.w]);

    atomicAdd(&q2[d.x], fmaf(sA1, p0.y, p0.x));
    atomicAdd(&q2[d.y], fmaf(sA1, p1.y, p1.x));
    atomicAdd(&q2[d.z], fmaf(sA1, p2.y, p2.x));
    atomicAdd(&q2[d.w], fmaf(sA1, p3.y, p3.x));
}

// ---------------------------------------------------------------------------
// 6. Final: A2 = c + sA1*q1;
//    A3 = A2 + t2 + sA2*q2 + deg*(b2 + wd2.z0 + sB2*A2);  out_z = z0 + A3
// ---------------------------------------------------------------------------
__global__ void final_kernel(const float4* __restrict__ z0,
                             const float4* __restrict__ T,
                             const float2* __restrict__ P,
                             const float* __restrict__ q2,
                             float4* __restrict__ out) {
    pdl_wait();
    int n = blockIdx.x * blockDim.x + threadIdx.x;
    if (n >= N_NODES) return;
    const float* wc = g_wc + 32;    // layer 2
    float sA1 = g_wc[16 + 13];
    float4 z = z0[n];
    float4 tt = T[n];
    float2 p = P[n];
    float a2 = fmaf(sA1, p.y, p.x);
    float pd = wc[12] + wc[4]*z.x + wc[5]*z.y + wc[6]*z.z + wc[7]*z.w
             + wc[14] * a2;
    float a3 = a2 + tt.z + wc[13] * q2[n] + tt.w * pd;
    out[n] = make_float4(z.x + a3, z.y + a3, z.z + a3, z.w + a3);
}

// ---------------------------------------------------------------------------
// PDL launch helper (serialization only — proven round-7 config)
// ---------------------------------------------------------------------------
template <typename... Args>
static void launch_pdl(void (*kern)(Args...), dim3 grid, dim3 block,
                       Args... args) {
    cudaLaunchAttribute attr[1];
    attr[0].id = cudaLaunchAttributeProgrammaticStreamSerialization;
    attr[0].val.programmaticStreamSerializationAllowed = 1;
    cudaLaunchConfig_t cfg = {};
    cfg.gridDim = grid;
    cfg.blockDim = block;
    cfg.dynamicSmemBytes = 0;
    cfg.stream = 0;
    cfg.attrs = attr;
    cfg.numAttrs = 1;
    cudaLaunchKernelEx(&cfg, kern, args...);
}

// ---------------------------------------------------------------------------
extern "C" void kernel_launch(void* const* d_in, const int* in_sizes, int n_in,
                              void* d_out, int out_size) {
    const float* z    = (const float*)d_in[0];
    const float* r    = (const float*)d_in[1];
    const float* rhat = (const float*)d_in[2];
    const float* W    = (const float*)d_in[3];
    const float* b    = (const float*)d_in[4];
    const int*   src  = (const int*)d_in[5];
    const int*   dst  = (const int*)d_in[6];
    float* out = (float*)d_out;

    float4 *T; float *A1, *q2; float2 *P;
    cudaGetSymbolAddress((void**)&T,  g_T);
    cudaGetSymbolAddress((void**)&A1, g_A1);
    cudaGetSymbolAddress((void**)&P,  g_P);
    cudaGetSymbolAddress((void**)&q2, g_q2);

    const dim3 blk(256);
    const dim3 NODE_GRID((N_NODES + 255) / 256);
    const dim3 EDGE_GRID(N_EDGES / 4 / 256);   // exact: 6250

    init_kernel<<<NODE_GRID, blk>>>(W, b, T, q2);

    launch_pdl(heavy_edge_kernel, EDGE_GRID, blk,
               (const int4*)src, (const int4*)dst,
               (const float4*)r, (const float4*)rhat,
               (const float4*)z, T);

    launch_pdl(node0_kernel, NODE_GRID, blk,
               (const float4*)z, (const float4*)T, A1, P, (float4*)out);

    launch_pdl(light1_kernel, EDGE_GRID, blk,
               (const int4*)src, (const int4*)dst, (const float*)A1, P);

    launch_pdl(light2_kernel, EDGE_GRID, blk,
               (const int4*)src, (const int4*)dst, (const float2*)P, q2);

    launch_pdl(final_kernel, NODE_GRID, blk,
               (const float4*)z, (const float4*)T, (const float2*)P,
               (const float*)q2, (float4*)out);
}